// round 6
// baseline (speedup 1.0000x reference)
#include <cuda_runtime.h>
#include <math.h>

// Shapes fixed: pred/target = [4,1,96,96,96] fp32, out = scalar fp32.
#define NB      23
#define NBIN    24            // padded bins (bin 23 weight = 0)
#define SROW    28            // shared row stride in floats (16B-aligned, 112B rows)
#define BT      256           // threads/block
#define NGRP    16            // 16-thread groups per block (4x4 over 24x24, 6x6 tiles)
#define STAGES  32
#define VPB     (BT*STAGES)   // 8192 voxels per block
#define BPB     108           // blocks per batch: 108*8192 = 884736
#define BATCH   4
#define NVOX    884736
#define CELLS   (NBIN*NBIN)   // 576
#define RROW    584           // group-reduction scratch row stride (floats)
#define K2EXP   (-1396.5287995805166f)   // -968 * log2(e)
#define ABUF    (BT*SROW)                // floats per weight array (7168)
#define SMEM_BYTES (2*ABUF*4)            // 57344 B (single-buffered wa/wb)

__device__ double g_bpart[(size_t)BATCH * BPB * CELLS];  // per-block partial pab, ~2 MB
__device__ double g_mi[BATCH];

__device__ __forceinline__ float ex2f(float x) {
    float r;
    asm("ex2.approx.ftz.f32 %0, %1;" : "=f"(r) : "f"(x));
    return r;
}
__device__ __forceinline__ unsigned long long dupf(float x) {
    unsigned long long r;
    unsigned u = __float_as_uint(x);
    asm("mov.b64 %0, {%1, %1};" : "=l"(r) : "r"(u));
    return r;
}
__device__ __forceinline__ void ffma2(unsigned long long& d,
                                      unsigned long long a,
                                      unsigned long long b) {
    asm("fma.rn.f32x2 %0, %1, %2, %0;" : "+l"(d) : "l"(a), "l"(b));
}

extern __shared__ float smemf[];   // [waS | wbS] (also reused as reduction scratch)

__global__ __launch_bounds__(BT, 3)
void mi_main(const float* __restrict__ pred, const float* __restrict__ target)
{
    float* waS = smemf;
    float* wbS = smemf + ABUF;

    const int tid    = threadIdx.x;
    const int b      = blockIdx.y;
    const int blk    = blockIdx.x;
    const int g      = tid >> 4;          // group 0..15
    const int lane16 = tid & 15;
    const int gi     = lane16 & 3;        // i-tile: rows gi*6 .. gi*6+5
    const int gj     = lane16 >> 2;       // j-tile: cols gj*6 .. gj*6+5

    const float* __restrict__ px = pred   + (size_t)b * NVOX + (size_t)blk * VPB;
    const float* __restrict__ py = target + (size_t)b * NVOX + (size_t)blk * VPB;

    // 6x6 tile as 6x3 packed f32x2 accumulators (j-pairs)
    unsigned long long acc[6][3];
    #pragma unroll
    for (int i = 0; i < 6; ++i)
        #pragma unroll
        for (int j = 0; j < 3; ++j) acc[i][j] = 0ULL;

    for (int s = 0; s < STAGES; ++s) {
        // ---------- gen phase ----------
        {
            const int idx = s * BT + tid;
            float x = px[idx]; x = fminf(fmaxf(x, 0.0f), 1.0f);
            float y = py[idx]; y = fminf(fmaxf(y, 0.0f), 1.0f);

            // wa: streamed by quads, stored raw (unscaled)
            float Sa = 0.0f;
            #pragma unroll
            for (int q = 0; q < 6; ++q) {
                float w[4];
                #pragma unroll
                for (int r = 0; r < 4; ++r) {
                    const int i = 4 * q + r;
                    if (i < NB) {
                        const float d = x - (float)(i * (1.0 / 22.0));
                        w[r] = ex2f(K2EXP * d * d);
                    } else {
                        w[r] = 0.0f;
                    }
                }
                Sa += ((w[0] + w[1]) + (w[2] + w[3]));
                *(float4*)&waS[tid * SROW + 4 * q] = make_float4(w[0], w[1], w[2], w[3]);
            }

            // wb: streamed by quads, stored raw; Sb summed on the fly
            float Sb = 0.0f;
            #pragma unroll
            for (int q = 0; q < 6; ++q) {
                float w[4];
                #pragma unroll
                for (int r = 0; r < 4; ++r) {
                    const int i = 4 * q + r;
                    if (i < NB) {
                        const float d = y - (float)(i * (1.0 / 22.0));
                        w[r] = ex2f(K2EXP * d * d);
                    } else {
                        w[r] = 0.0f;
                    }
                }
                Sb += ((w[0] + w[1]) + (w[2] + w[3]));
                *(float4*)&wbS[tid * SROW + 4 * q] = make_float4(w[0], w[1], w[2], w[3]);
            }

            // rescale wb in place by 1/(Sa*Sb) (correctly-rounded reciprocal)
            const float rs = 1.0f / (Sa * Sb);
            #pragma unroll
            for (int q = 0; q < 6; ++q) {
                float4 v = *(float4*)&wbS[tid * SROW + 4 * q];
                v.x *= rs; v.y *= rs; v.z *= rs; v.w *= rs;
                *(float4*)&wbS[tid * SROW + 4 * q] = v;
            }
        }
        __syncthreads();

        // ---------- MMA phase: 6x6 outer-product; group g handles voxels v*16+g ----------
        #pragma unroll 4
        for (int v = 0; v < 16; ++v) {
            const int t = v * NGRP + g;

            const float* war = &waS[t * SROW + gi * 6];
            const float2 a01 = *(const float2*)(war);
            const float2 a23 = *(const float2*)(war + 2);
            const float2 a45 = *(const float2*)(war + 4);
            unsigned long long A[6];
            A[0] = dupf(a01.x); A[1] = dupf(a01.y);
            A[2] = dupf(a23.x); A[3] = dupf(a23.y);
            A[4] = dupf(a45.x); A[5] = dupf(a45.y);

            const float* wbr = &wbS[t * SROW + gj * 6];
            unsigned long long Bv[3];
            Bv[0] = *(const unsigned long long*)(wbr);
            Bv[1] = *(const unsigned long long*)(wbr + 2);
            Bv[2] = *(const unsigned long long*)(wbr + 4);

            #pragma unroll
            for (int ii = 0; ii < 6; ++ii)
                #pragma unroll
                for (int jp = 0; jp < 3; ++jp)
                    ffma2(acc[ii][jp], A[ii], Bv[jp]);
        }
        __syncthreads();
    }

    // ---- in-block reduction of the 16 group tiles (reuse smem as scratch) ----
    float* sred = smemf;   // 16 * RROW * 4 = 37376 B <= 57344 B
    #pragma unroll
    for (int ii = 0; ii < 6; ++ii)
        #pragma unroll
        for (int jp = 0; jp < 3; ++jp) {
            const int cell = (gi * 6 + ii) * NBIN + gj * 6 + 2 * jp;
            *(unsigned long long*)&sred[g * RROW + cell] = acc[ii][jp];
        }
    __syncthreads();

    double* outp = g_bpart + ((size_t)b * BPB + blk) * CELLS;
    for (int c = tid; c < CELLS; c += BT) {
        float ssum = 0.0f;
        #pragma unroll
        for (int g2 = 0; g2 < NGRP; ++g2) ssum += sred[g2 * RROW + c];
        outp[c] = (double)ssum;
    }
}

// Per-batch: sum 108 block partials, marginals, MI — all in double. Grid = 4.
__global__ __launch_bounds__(CELLS)
void mi_batch()
{
    __shared__ double pabS[CELLS];
    __shared__ double paS[NBIN], pbS[NBIN];
    __shared__ double red[CELLS];
    const int b = blockIdx.x;
    const int c = threadIdx.x;
    const double invN = 1.0 / (double)NVOX;

    double t = 0.0;
    #pragma unroll 4
    for (int blk = 0; blk < BPB; ++blk)
        t += g_bpart[((size_t)b * BPB + blk) * CELLS + c];
    pabS[c] = t;
    __syncthreads();

    if (c < NB) {
        double m = 0.0;
        for (int j = 0; j < NB; ++j) m += pabS[c * NBIN + j];
        paS[c] = m * invN;
    } else if (c >= 32 && c < 32 + NB) {
        const int j = c - 32;
        double m = 0.0;
        for (int i = 0; i < NB; ++i) m += pabS[i * NBIN + j];
        pbS[j] = m * invN;
    }
    __syncthreads();

    const int i = c / NBIN, j = c % NBIN;
    double term = 0.0;
    if (i < NB && j < NB) {
        const double pab  = pabS[c] * invN;
        const double papb = paS[i] * pbS[j];
        term = pab * log((pab + 1e-7) / (papb + 1e-7) + 1e-7);
    }
    red[c] = term;
    __syncthreads();

    if (c < 64) red[c] += red[c + 512];
    __syncthreads();
    for (int o = 256; o > 0; o >>= 1) {
        if (c < o) red[c] += red[c + o];
        __syncthreads();
    }
    if (c == 0) g_mi[b] = red[0];
}

__global__ void mi_final(float* __restrict__ out)
{
    double s = 0.0;
    for (int b = 0; b < BATCH; ++b) s += g_mi[b];
    out[0] = (float)(-s / (double)BATCH);
}

extern "C" void kernel_launch(void* const* d_in, const int* in_sizes, int n_in,
                              void* d_out, int out_size)
{
    (void)in_sizes; (void)n_in; (void)out_size;
    const float* pred   = (const float*)d_in[0];
    const float* target = (const float*)d_in[1];

    cudaFuncSetAttribute(mi_main, cudaFuncAttributeMaxDynamicSharedMemorySize, SMEM_BYTES);

    dim3 g1(BPB, BATCH);
    mi_main<<<g1, BT, SMEM_BYTES>>>(pred, target);

    mi_batch<<<BATCH, CELLS>>>();

    mi_final<<<1, 1>>>((float*)d_out);
}